// round 4
// baseline (speedup 1.0000x reference)
#include <cuda_runtime.h>
#include <cuda_fp16.h>
#include <math.h>

#define B     64
#define P     196
#define D     2048
#define A_DIM 512
#define H     512
#define E     512
#define V     10000
#define VPAD  10048
#define T     19
#define LCAP  20
#define XH    3072
#define G4    2048
#define NSMALL 2560
#define KSPLIT 4
#define KS_LEN (XH/KSPLIT)   /* 768 */

// ---------------- device scratch ---------------------------------------------
__device__ __half g_featsh[(size_t)B*P*D];
__device__ __half g_att1h[(size_t)B*P*A_DIM];
__device__ __half g_Wcath[(size_t)G4*XH];
__device__ __half g_clswh[(size_t)VPAD*H];
__device__ __half g_encwh[(size_t)A_DIM*D];
__device__ __half g_smallw[(size_t)NSMALL*H];
__device__ __half g_hcwh[(size_t)2*H*D];
__device__ __half g_meanfh[B*D];
__device__ __half g_embh[(size_t)B*T*E];
__device__ __half g_xhh[(size_t)B*XH];
__device__ float  g_small_out[(size_t)B*NSMALL];
__device__ float  g_smallb[NSMALL];
__device__ float  g_hcb[2*H];
__device__ float  g_bcat[G4];
__device__ float  g_h0[B*H];
__device__ float  g_c[B*H];
__device__ float  g_e[B*P];
__device__ float  g_gparts[(size_t)KSPLIT*B*G4];
__device__ volatile unsigned g_bar;

// ---------------- helpers -----------------------------------------------------
__device__ __forceinline__ void st_half4(__half* dst, float4 v)
{
    ((__half2*)dst)[0] = __floats2half2_rn(v.x, v.y);
    ((__half2*)dst)[1] = __floats2half2_rn(v.z, v.w);
}

__global__ void k_zero() { if (threadIdx.x == 0) *(unsigned*)&g_bar = 0u; }

// fused features fp32->fp16 + mean (read features once)
__global__ void k_f2h_mean(const float* __restrict__ f)
{
    int i = blockIdx.x * blockDim.x + threadIdx.x;
    if (i >= B*D) return;
    int b = i >> 11, d = i & (D-1);
    const float* p = f + (size_t)b*P*D + d;
    __half* o = g_featsh + (size_t)b*P*D + d;
    float s = 0.f;
    #pragma unroll 4
    for (int q = 0; q < P; q++) {
        float v = p[(size_t)q*D];
        s += v;
        o[(size_t)q*D] = __float2half(v);
    }
    g_meanfh[i] = __float2half(s * (1.f/196.f));
}

__global__ void k_ench(const float* __restrict__ w)
{
    size_t i = ((size_t)blockIdx.x * blockDim.x + threadIdx.x) * 4;
    if (i < (size_t)A_DIM*D)
        st_half4(g_encwh + i, *(const float4*)(w + i));
}

// grid (3, G4), block 256: each thread 4 consecutive cols; no div/mod
__global__ void k_wcath(const float* __restrict__ W_ih, const float* __restrict__ b_ih,
                        const float* __restrict__ W_hh, const float* __restrict__ b_hh)
{
    int j = blockIdx.y;
    int k = blockIdx.x * 1024 + threadIdx.x * 4;
    float4 v = (k < E + D) ? *(const float4*)(W_ih + (size_t)j*(E+D) + k)
                           : *(const float4*)(W_hh + (size_t)j*H + (k - (E+D)));
    st_half4(g_Wcath + (size_t)j*XH + k, v);
    if (k == 0) g_bcat[j] = b_ih[j] + b_hh[j];
}

// grid VPAD, block 128
__global__ void k_clsh(const float* __restrict__ cls_w)
{
    int n = blockIdx.x, k = threadIdx.x * 4;
    float4 v = make_float4(0.f, 0.f, 0.f, 0.f);
    if (n < V) v = *(const float4*)(cls_w + (size_t)n*H + k);
    st_half4(g_clswh + (size_t)n*H + k, v);
}

// grid NSMALL, block 128
__global__ void k_smallwh(const float* __restrict__ dec_w, const float* __restrict__ dec_b,
                          const float* __restrict__ fb_w,  const float* __restrict__ fb_b)
{
    int n = blockIdx.x, k = threadIdx.x * 4;
    const float* src = (n < A_DIM) ? dec_w + (size_t)n*H : fb_w + (size_t)(n - A_DIM)*H;
    st_half4(g_smallw + (size_t)n*H + k, *(const float4*)(src + k));
    if (k == 0) g_smallb[n] = (n < A_DIM) ? dec_b[n] : fb_b[n - A_DIM];
}

// grid 2*H, block 256 (8 cols each)
__global__ void k_hcwh(const float* __restrict__ h_fc_w, const float* __restrict__ h_fc_b,
                       const float* __restrict__ c_fc_w, const float* __restrict__ c_fc_b)
{
    int n = blockIdx.x, k = threadIdx.x * 8;
    const float* src = (n < H) ? h_fc_w + (size_t)n*D : c_fc_w + (size_t)(n - H)*D;
    st_half4(g_hcwh + (size_t)n*D + k,     *(const float4*)(src + k));
    st_half4(g_hcwh + (size_t)n*D + k + 4, *(const float4*)(src + k + 4));
    if (k == 0) g_hcb[n] = (n < H) ? h_fc_b[n] : c_fc_b[n - H];
}

__global__ void k_embh(const float* __restrict__ emb, const int* __restrict__ captions)
{
    int i = blockIdx.x * blockDim.x + threadIdx.x;
    if (i < B*T*E) {
        int e  = i & (E-1);
        int bt = i >> 9;
        int b = bt / T, t = bt % T;
        int tok = captions[b*LCAP + t];
        g_embh[i] = __float2half(emb[(size_t)tok*E + e]);
    }
}

__global__ void k_initxh()
{
    int i = blockIdx.x * blockDim.x + threadIdx.x;
    if (i < B*H) {
        int b = i >> 9, j = i & (H-1);
        g_xhh[b*XH + j]         = g_embh[(size_t)(b*T + 0)*E + j];
        g_xhh[b*XH + E + D + j] = __float2half(g_h0[i]);
    }
}

// ---------------- HMMA core ----------------------------------------------------
__device__ __forceinline__ void mma16816(float c[4], const unsigned a[4], const unsigned b[2])
{
    asm volatile(
        "mma.sync.aligned.m16n8k16.row.col.f32.f16.f16.f32 "
        "{%0,%1,%2,%3}, {%4,%5,%6,%7}, {%8,%9}, {%0,%1,%2,%3};"
        : "+f"(c[0]), "+f"(c[1]), "+f"(c[2]), "+f"(c[3])
        : "r"(a[0]), "r"(a[1]), "r"(a[2]), "r"(a[3]), "r"(b[0]), "r"(b[1]));
}

struct SmemT { __half As[64][40]; __half Ws[64][40]; };

// C(64, 64) += A(64, K) @ W(64, K)^T ; A/W already offset to their tile bases.
__device__ __forceinline__ void hmma_tile(
    const __half* __restrict__ Aptr, int ldA,
    const __half* __restrict__ Wptr, int ldW,
    SmemT* sm, float acc[2][2][4], int K)
{
    const int tid  = threadIdx.x;
    const int lane = tid & 31;
    const int wid  = tid >> 5;
    const int wm   = wid >> 2;
    const int wn   = wid & 3;
    const int grp  = lane >> 2;
    const int qp   = lane & 3;
    const int lrow = tid >> 2;
    const int lcol = (tid & 3) * 8;

    for (int kc = 0; kc < K; kc += 32) {
        uint4 av = *(const uint4*)(Aptr + (size_t)lrow*ldA + kc + lcol);
        uint4 wv = *(const uint4*)(Wptr + (size_t)lrow*ldW + kc + lcol);
        __syncthreads();
        *(uint4*)&sm->As[lrow][lcol] = av;
        *(uint4*)&sm->Ws[lrow][lcol] = wv;
        __syncthreads();
        #pragma unroll
        for (int ks = 0; ks < 2; ks++) {
            const int kb = 16*ks + 2*qp;
            unsigned afr[2][4], bfr[2][2];
            #pragma unroll
            for (int mf = 0; mf < 2; mf++) {
                const int r = 32*wm + 16*mf + grp;
                afr[mf][0] = *(const unsigned*)&sm->As[r    ][kb    ];
                afr[mf][1] = *(const unsigned*)&sm->As[r + 8][kb    ];
                afr[mf][2] = *(const unsigned*)&sm->As[r    ][kb + 8];
                afr[mf][3] = *(const unsigned*)&sm->As[r + 8][kb + 8];
            }
            #pragma unroll
            for (int nf = 0; nf < 2; nf++) {
                const int r = 16*wn + 8*nf + grp;
                bfr[nf][0] = *(const unsigned*)&sm->Ws[r][kb    ];
                bfr[nf][1] = *(const unsigned*)&sm->Ws[r][kb + 8];
            }
            #pragma unroll
            for (int mf = 0; mf < 2; mf++)
                #pragma unroll
                for (int nf = 0; nf < 2; nf++)
                    mma16816(acc[mf][nf], afr[mf], bfr[nf]);
        }
    }
}

// standalone HMMA for att1 (mode 3) and h0/c0 (mode 4)
__global__ void __launch_bounds__(256) k_hgemm(
    const __half* __restrict__ A, int ldA,
    const __half* __restrict__ W, int ldW,
    const float* __restrict__ bias, int K, int mode)
{
    __shared__ SmemT sm;
    const int tid  = threadIdx.x;
    const int lane = tid & 31;
    const int wid  = tid >> 5;
    const int wm = wid >> 2, wn = wid & 3, grp = lane >> 2, qp = lane & 3;
    const int n0 = blockIdx.x * 64;
    const int m0 = blockIdx.z * 64;
    float acc[2][2][4] = {};
    hmma_tile(A + (size_t)m0*ldA, ldA, W + (size_t)n0*ldW, ldW, &sm, acc, K);
    #pragma unroll
    for (int mf = 0; mf < 2; mf++)
        #pragma unroll
        for (int nf = 0; nf < 2; nf++)
            #pragma unroll
            for (int q = 0; q < 4; q++) {
                int m = m0 + 32*wm + 16*mf + grp + (q >> 1)*8;
                int n = n0 + 16*wn + 8*nf + 2*qp + (q & 1);
                float v = acc[mf][nf][q] + bias[n];
                if (mode == 3) {
                    g_att1h[(size_t)m*A_DIM + n] = __float2half(v);
                } else { // mode 4: h0 / c0
                    if (n < H) g_h0[(size_t)m*H + n] = v;
                    else       g_c [(size_t)m*H + n - H] = v;
                }
            }
}

// ---------------- persistent decode loop ---------------------------------------
__device__ __forceinline__ void gbar(int nblk, int& target)
{
    __syncthreads();
    target += nblk;
    if (threadIdx.x == 0) {
        __threadfence();
        atomicAdd((unsigned*)&g_bar, 1u);
        while (g_bar < (unsigned)target) { }
        __threadfence();
    }
    __syncthreads();
}

__global__ void __launch_bounds__(256, 1) k_decode(
    const int*   __restrict__ lengths,
    const float* __restrict__ attw,
    const float* __restrict__ attb,
    const float* __restrict__ cls_b,
    float* __restrict__ outy,
    float* __restrict__ outa)
{
    __shared__ SmemT sm;
    __shared__ float sred[256];
    __shared__ float sal[P];
    const int nblk = gridDim.x;
    const int bid  = blockIdx.x;
    const int tid  = threadIdx.x;
    const int lane = tid & 31;
    const int wid  = tid >> 5;
    const int wm = wid >> 2, wn = wid & 3, grp = lane >> 2, qp = lane & 3;
    int target = 0;

    for (int t = 0; t < T; t++) {
        // ---- Phase A: att2|gate small GEMM (tiles 0..39) + cls(t-1) (tiles 40..196)
        const int ntA = (t > 0) ? 197 : 40;
        for (int tile = bid; tile < ntA; tile += nblk) {
            float acc[2][2][4] = {};
            if (tile < 40) {
                const int n0 = tile * 64;
                hmma_tile(g_xhh + (E + D), XH, g_smallw + (size_t)n0*H, H, &sm, acc, H);
                #pragma unroll
                for (int mf = 0; mf < 2; mf++)
                    #pragma unroll
                    for (int nf = 0; nf < 2; nf++)
                        #pragma unroll
                        for (int q = 0; q < 4; q++) {
                            int m = 32*wm + 16*mf + grp + (q >> 1)*8;
                            int n = n0 + 16*wn + 8*nf + 2*qp + (q & 1);
                            float v = acc[mf][nf][q] + g_smallb[n];
                            if (n >= A_DIM) v = 1.f / (1.f + expf(-v));
                            g_small_out[(size_t)m*NSMALL + n] = v;
                        }
            } else {
                const int n0 = (tile - 40) * 64;
                hmma_tile(g_xhh + (E + D), XH, g_clswh + (size_t)n0*H, H, &sm, acc, H);
                const int tp = t - 1;
                #pragma unroll
                for (int mf = 0; mf < 2; mf++)
                    #pragma unroll
                    for (int nf = 0; nf < 2; nf++)
                        #pragma unroll
                        for (int q = 0; q < 4; q++) {
                            int m = 32*wm + 16*mf + grp + (q >> 1)*8;
                            int n = n0 + 16*wn + 8*nf + 2*qp + (q & 1);
                            if (n < V) {
                                int act = tp < (lengths[m] - 1);
                                outy[(size_t)m*T*V + (size_t)tp*V + n] =
                                    act ? (acc[mf][nf][q] + cls_b[n]) : 0.f;
                            }
                        }
            }
        }
        gbar(nblk, target);

        // ---- Phase B: e scores (one warp per (b,p))
        for (int idx = bid*8 + wid; idx < B*P; idx += nblk*8) {
            const int b = idx / P;
            const __half* a1 = g_att1h + (size_t)idx * A_DIM;
            const float*  a2 = g_small_out + (size_t)b * NSMALL;
            float s = 0.f;
            #pragma unroll 4
            for (int a = lane; a < A_DIM; a += 32) {
                float v = __half2float(a1[a]) + a2[a];
                if (v > 0.f) s += v * attw[a];
            }
            #pragma unroll
            for (int o = 16; o; o >>= 1) s += __shfl_xor_sync(0xffffffffu, s, o);
            if (lane == 0) g_e[idx] = s + attb[0];
        }
        gbar(nblk, target);

        // ---- Phase C: softmax + awe (256 tiles = (b, chunk))
        for (int tile = bid; tile < B*4; tile += nblk) {
            const int b = tile >> 2, chunk = tile & 3;
            float ev = (tid < P) ? g_e[b*P + tid] : -1e30f;
            sred[tid] = ev; __syncthreads();
            for (int s2 = 128; s2 > 0; s2 >>= 1) {
                if (tid < s2) sred[tid] = fmaxf(sred[tid], sred[tid + s2]);
                __syncthreads();
            }
            float mx = sred[0]; __syncthreads();
            float ex = (tid < P) ? expf(ev - mx) : 0.f;
            sred[tid] = ex; __syncthreads();
            for (int s2 = 128; s2 > 0; s2 >>= 1) {
                if (tid < s2) sred[tid] += sred[tid + s2];
                __syncthreads();
            }
            float inv = 1.f / sred[0];
            if (tid < P) sal[tid] = ex * inv;
            __syncthreads();

            const __half2* fp2 = (const __half2*)g_featsh + (size_t)b*P*(D/2) + chunk*256 + tid;
            float2 acc2 = make_float2(0.f, 0.f);
            #pragma unroll 4
            for (int p = 0; p < P; p++) {
                float2 f = __half22float2(fp2[(size_t)p*(D/2)]);
                acc2.x += sal[p] * f.x;
                acc2.y += sal[p] * f.y;
            }
            const int d = chunk*512 + 2*tid;
            acc2.x *= g_small_out[(size_t)b*NSMALL + A_DIM + d];
            acc2.y *= g_small_out[(size_t)b*NSMALL + A_DIM + d + 1];
            *(__half2*)&g_xhh[(size_t)b*XH + E + d] = __floats2half2_rn(acc2.x, acc2.y);

            if (chunk == 0 && tid < P) {
                int act = t < (lengths[b] - 1);
                outa[((size_t)b*T + t)*P + tid] = act ? sal[tid] : 0.f;
            }
            __syncthreads();
        }
        gbar(nblk, target);

        // ---- Phase D: gates GEMM, 32 n-tiles x 4 K-splits
        for (int tile = bid; tile < 32*KSPLIT; tile += nblk) {
            const int n0 = (tile & 31) * 64;
            const int ks = tile >> 5;
            float acc[2][2][4] = {};
            hmma_tile(g_xhh + ks*KS_LEN, XH,
                      g_Wcath + (size_t)n0*XH + ks*KS_LEN, XH, &sm, acc, KS_LEN);
            #pragma unroll
            for (int mf = 0; mf < 2; mf++)
                #pragma unroll
                for (int nf = 0; nf < 2; nf++)
                    #pragma unroll
                    for (int q = 0; q < 4; q++) {
                        int m = 32*wm + 16*mf + grp + (q >> 1)*8;
                        int n = n0 + 16*wn + 8*nf + 2*qp + (q & 1);
                        g_gparts[(size_t)ks*B*G4 + (size_t)m*G4 + n] = acc[mf][nf][q];
                    }
        }
        gbar(nblk, target);

        // ---- Phase E: LSTM pointwise + next-step state staging
        for (int i = bid*256 + tid; i < B*H; i += nblk*256) {
            const int b = i >> 9, j = i & (H-1);
            float gi = g_bcat[j], gf = g_bcat[j + H], gg = g_bcat[j + 2*H], go = g_bcat[j + 3*H];
            #pragma unroll
            for (int s = 0; s < KSPLIT; s++) {
                const float* pp = g_gparts + (size_t)s*B*G4 + (size_t)b*G4;
                gi += pp[j]; gf += pp[j + H]; gg += pp[j + 2*H]; go += pp[j + 3*H];
            }
            float si = 1.f / (1.f + expf(-gi));
            float sf = 1.f / (1.f + expf(-gf));
            float so = 1.f / (1.f + expf(-go));
            float c2 = sf * g_c[i] + si * tanhf(gg);
            float h2 = so * tanhf(c2);
            g_c[i] = c2;
            g_xhh[(size_t)b*XH + E + D + j] = __float2half(h2);
            if (t + 1 < T) g_xhh[(size_t)b*XH + j] = g_embh[(size_t)(b*T + (t+1))*E + j];
        }
        gbar(nblk, target);
    }

    // ---- final cls for t = T-1
    for (int tile = bid; tile < 157; tile += nblk) {
        const int n0 = tile * 64;
        float acc[2][2][4] = {};
        hmma_tile(g_xhh + (E + D), XH, g_clswh + (size_t)n0*H, H, &sm, acc, H);
        const int tp = T - 1;
        #pragma unroll
        for (int mf = 0; mf < 2; mf++)
            #pragma unroll
            for (int nf = 0; nf < 2; nf++)
                #pragma unroll
                for (int q = 0; q < 4; q++) {
                    int m = 32*wm + 16*mf + grp + (q >> 1)*8;
                    int n = n0 + 16*wn + 8*nf + 2*qp + (q & 1);
                    if (n < V) {
                        int act = tp < (lengths[m] - 1);
                        outy[(size_t)m*T*V + (size_t)tp*V + n] =
                            act ? (acc[mf][nf][q] + cls_b[n]) : 0.f;
                    }
                }
    }
}

// ---------------- host driver ---------------------------------------------------
extern "C" void kernel_launch(void* const* d_in, const int* in_sizes, int n_in,
                              void* d_out, int out_size)
{
    const float* features = (const float*)d_in[0];
    const int*   captions = (const int*)  d_in[1];
    const int*   lengths  = (const int*)  d_in[2];
    const float* emb      = (const float*)d_in[3];
    const float* W_ih     = (const float*)d_in[4];
    const float* b_ih     = (const float*)d_in[5];
    const float* W_hh     = (const float*)d_in[6];
    const float* b_hh     = (const float*)d_in[7];
    const float* h_fc_w   = (const float*)d_in[8];
    const float* h_fc_b   = (const float*)d_in[9];
    const float* c_fc_w   = (const float*)d_in[10];
    const float* c_fc_b   = (const float*)d_in[11];
    const float* f_beta_w = (const float*)d_in[12];
    const float* f_beta_b = (const float*)d_in[13];
    const float* cls_w    = (const float*)d_in[14];
    const float* cls_b    = (const float*)d_in[15];
    const float* enc_w    = (const float*)d_in[16];
    const float* enc_b    = (const float*)d_in[17];
    const float* dec_w    = (const float*)d_in[18];
    const float* dec_b    = (const float*)d_in[19];
    const float* att_w    = (const float*)d_in[20];
    const float* att_b    = (const float*)d_in[21];

    float* outy = (float*)d_out;
    float* outa = outy + (size_t)B*T*V;

    __half *p_featsh, *p_encwh, *p_meanfh, *p_hcwh;
    float  *p_hcb;
    cudaGetSymbolAddress((void**)&p_featsh, g_featsh);
    cudaGetSymbolAddress((void**)&p_encwh,  g_encwh);
    cudaGetSymbolAddress((void**)&p_meanfh, g_meanfh);
    cudaGetSymbolAddress((void**)&p_hcwh,   g_hcwh);
    cudaGetSymbolAddress((void**)&p_hcb,    g_hcb);

    int nsm = 148;
    cudaDeviceGetAttribute(&nsm, cudaDevAttrMultiProcessorCount, 0);

    // launch order keeps att1 at index 5 for the ncu -s 5 -c 1 window
    k_zero    <<<1, 32>>>();
    k_f2h_mean<<<(B*D + 255)/256, 256>>>(features);
    k_ench    <<<(A_DIM*D/4 + 255)/256, 256>>>(enc_w);
    k_wcath   <<<dim3(3, G4), 256>>>(W_ih, b_ih, W_hh, b_hh);
    k_clsh    <<<VPAD, 128>>>(cls_w);
    k_hgemm   <<<dim3(A_DIM/64, 1, (B*P)/64), 256>>>(p_featsh, D, p_encwh, D, enc_b, D, 3);
    k_embh    <<<(B*T*E + 255)/256, 256>>>(emb, captions);
    k_smallwh <<<NSMALL, 128>>>(dec_w, dec_b, f_beta_w, f_beta_b);
    k_hcwh    <<<2*H, 256>>>(h_fc_w, h_fc_b, c_fc_w, c_fc_b);
    k_hgemm   <<<dim3(2*H/64, 1, 1), 256>>>(p_meanfh, D, p_hcwh, D, p_hcb, D, 4);
    k_initxh  <<<(B*H + 255)/256, 256>>>();
    k_decode  <<<nsm, 256>>>(lengths, att_w, att_b, cls_b, outy, outa);
}

// round 5
// speedup vs baseline: 1.0221x; 1.0221x over previous
#include <cuda_runtime.h>
#include <cuda_fp16.h>
#include <math.h>

#define B     64
#define P     196
#define D     2048
#define A_DIM 512
#define H     512
#define E     512
#define V     10000
#define VPAD  10048
#define T     19
#define LCAP  20
#define XH    3072
#define G4    2048
#define NSMALL 2560
#define KSPLIT 4
#define KS_LEN (XH/KSPLIT)   /* 768 */

// ---------------- device scratch ---------------------------------------------
__device__ __half g_featsh[(size_t)B*P*D];
__device__ __half g_att1h[(size_t)B*P*A_DIM];
__device__ __half g_Wcath[(size_t)G4*XH];
__device__ __half g_clswh[(size_t)VPAD*H];
__device__ __half g_encwh[(size_t)A_DIM*D];
__device__ __half g_smallw[(size_t)NSMALL*H];
__device__ __half g_hcwh[(size_t)2*H*D];
__device__ __half g_meanfh[B*D];
__device__ __half g_embh[(size_t)B*T*E];
__device__ __half g_xhh[(size_t)B*XH];
__device__ float  g_small_out[(size_t)B*NSMALL];
__device__ float  g_smallb[NSMALL];
__device__ float  g_hcb[2*H];
__device__ float  g_bcat[G4];
__device__ float  g_h0[B*H];
__device__ float  g_c[B*H];
__device__ float  g_gparts[(size_t)KSPLIT*B*G4];
__device__ volatile unsigned g_bar;

// ---------------- helpers -----------------------------------------------------
__device__ __forceinline__ void st_half4(__half* dst, float4 v)
{
    ((__half2*)dst)[0] = __floats2half2_rn(v.x, v.y);
    ((__half2*)dst)[1] = __floats2half2_rn(v.z, v.w);
}

__global__ void k_zero() { if (threadIdx.x == 0) *(unsigned*)&g_bar = 0u; }

__global__ void k_f2h_mean(const float* __restrict__ f)
{
    int i = blockIdx.x * blockDim.x + threadIdx.x;
    if (i >= B*D) return;
    int b = i >> 11, d = i & (D-1);
    const float* p = f + (size_t)b*P*D + d;
    __half* o = g_featsh + (size_t)b*P*D + d;
    float s = 0.f;
    #pragma unroll 4
    for (int q = 0; q < P; q++) {
        float v = p[(size_t)q*D];
        s += v;
        o[(size_t)q*D] = __float2half(v);
    }
    g_meanfh[i] = __float2half(s * (1.f/196.f));
}

__global__ void k_ench(const float* __restrict__ w)
{
    size_t i = ((size_t)blockIdx.x * blockDim.x + threadIdx.x) * 4;
    if (i < (size_t)A_DIM*D)
        st_half4(g_encwh + i, *(const float4*)(w + i));
}

__global__ void k_wcath(const float* __restrict__ W_ih, const float* __restrict__ b_ih,
                        const float* __restrict__ W_hh, const float* __restrict__ b_hh)
{
    int j = blockIdx.y;
    int k = blockIdx.x * 1024 + threadIdx.x * 4;
    float4 v = (k < E + D) ? *(const float4*)(W_ih + (size_t)j*(E+D) + k)
                           : *(const float4*)(W_hh + (size_t)j*H + (k - (E+D)));
    st_half4(g_Wcath + (size_t)j*XH + k, v);
    if (k == 0) g_bcat[j] = b_ih[j] + b_hh[j];
}

__global__ void k_clsh(const float* __restrict__ cls_w)
{
    int n = blockIdx.x, k = threadIdx.x * 4;
    float4 v = make_float4(0.f, 0.f, 0.f, 0.f);
    if (n < V) v = *(const float4*)(cls_w + (size_t)n*H + k);
    st_half4(g_clswh + (size_t)n*H + k, v);
}

__global__ void k_smallwh(const float* __restrict__ dec_w, const float* __restrict__ dec_b,
                          const float* __restrict__ fb_w,  const float* __restrict__ fb_b)
{
    int n = blockIdx.x, k = threadIdx.x * 4;
    const float* src = (n < A_DIM) ? dec_w + (size_t)n*H : fb_w + (size_t)(n - A_DIM)*H;
    st_half4(g_smallw + (size_t)n*H + k, *(const float4*)(src + k));
    if (k == 0) g_smallb[n] = (n < A_DIM) ? dec_b[n] : fb_b[n - A_DIM];
}

__global__ void k_hcwh(const float* __restrict__ h_fc_w, const float* __restrict__ h_fc_b,
                       const float* __restrict__ c_fc_w, const float* __restrict__ c_fc_b)
{
    int n = blockIdx.x, k = threadIdx.x * 8;
    const float* src = (n < H) ? h_fc_w + (size_t)n*D : c_fc_w + (size_t)(n - H)*D;
    st_half4(g_hcwh + (size_t)n*D + k,     *(const float4*)(src + k));
    st_half4(g_hcwh + (size_t)n*D + k + 4, *(const float4*)(src + k + 4));
    if (k == 0) g_hcb[n] = (n < H) ? h_fc_b[n] : c_fc_b[n - H];
}

__global__ void k_embh(const float* __restrict__ emb, const int* __restrict__ captions)
{
    int i = blockIdx.x * blockDim.x + threadIdx.x;
    if (i < B*T*E) {
        int e  = i & (E-1);
        int bt = i >> 9;
        int b = bt / T, t = bt % T;
        int tok = captions[b*LCAP + t];
        g_embh[i] = __float2half(emb[(size_t)tok*E + e]);
    }
}

__global__ void k_initxh()
{
    int i = blockIdx.x * blockDim.x + threadIdx.x;
    if (i < B*H) {
        int b = i >> 9, j = i & (H-1);
        g_xhh[b*XH + j]         = g_embh[(size_t)(b*T + 0)*E + j];
        g_xhh[b*XH + E + D + j] = __float2half(g_h0[i]);
    }
}

// ---------------- HMMA core ----------------------------------------------------
__device__ __forceinline__ void mma16816(float c[4], const unsigned a[4], const unsigned b[2])
{
    asm volatile(
        "mma.sync.aligned.m16n8k16.row.col.f32.f16.f16.f32 "
        "{%0,%1,%2,%3}, {%4,%5,%6,%7}, {%8,%9}, {%0,%1,%2,%3};"
        : "+f"(c[0]), "+f"(c[1]), "+f"(c[2]), "+f"(c[3])
        : "r"(a[0]), "r"(a[1]), "r"(a[2]), "r"(a[3]), "r"(b[0]), "r"(b[1]));
}

struct SmemT { __half As[64][40]; __half Ws[64][40]; };

// C(64,64) = A(64,K) @ W(64,K)^T with register-prefetch double buffering.
__device__ __forceinline__ void hmma_tile(
    const __half* __restrict__ Aptr, int ldA,
    const __half* __restrict__ Wptr, int ldW,
    SmemT* sm, float acc[2][2][4], int K)
{
    const int tid  = threadIdx.x;
    const int lane = tid & 31;
    const int wid  = tid >> 5;
    const int wm   = wid >> 2;
    const int wn   = wid & 3;
    const int grp  = lane >> 2;
    const int qp   = lane & 3;
    const int lrow = tid >> 2;
    const int lcol = (tid & 3) * 8;

    const __half* ap = Aptr + (size_t)lrow*ldA + lcol;
    const __half* wp = Wptr + (size_t)lrow*ldW + lcol;

    uint4 av = *(const uint4*)ap;
    uint4 wv = *(const uint4*)wp;

    for (int kc = 0; kc < K; kc += 32) {
        __syncthreads();
        *(uint4*)&sm->As[lrow][lcol] = av;
        *(uint4*)&sm->Ws[lrow][lcol] = wv;
        __syncthreads();
        if (kc + 32 < K) {                       // prefetch next chunk
            av = *(const uint4*)(ap + kc + 32);
            wv = *(const uint4*)(wp + kc + 32);
        }
        #pragma unroll
        for (int ks = 0; ks < 2; ks++) {
            const int kb = 16*ks + 2*qp;
            unsigned afr[2][4], bfr[2][2];
            #pragma unroll
            for (int mf = 0; mf < 2; mf++) {
                const int r = 32*wm + 16*mf + grp;
                afr[mf][0] = *(const unsigned*)&sm->As[r    ][kb    ];
                afr[mf][1] = *(const unsigned*)&sm->As[r + 8][kb    ];
                afr[mf][2] = *(const unsigned*)&sm->As[r    ][kb + 8];
                afr[mf][3] = *(const unsigned*)&sm->As[r + 8][kb + 8];
            }
            #pragma unroll
            for (int nf = 0; nf < 2; nf++) {
                const int r = 16*wn + 8*nf + grp;
                bfr[nf][0] = *(const unsigned*)&sm->Ws[r][kb    ];
                bfr[nf][1] = *(const unsigned*)&sm->Ws[r][kb + 8];
            }
            #pragma unroll
            for (int mf = 0; mf < 2; mf++)
                #pragma unroll
                for (int nf = 0; nf < 2; nf++)
                    mma16816(acc[mf][nf], afr[mf], bfr[nf]);
        }
    }
}

// standalone HMMA for att1 (mode 3) and h0/c0 (mode 4)
__global__ void __launch_bounds__(256, 2) k_hgemm(
    const __half* __restrict__ A, int ldA,
    const __half* __restrict__ W, int ldW,
    const float* __restrict__ bias, int K, int mode)
{
    __shared__ SmemT sm;
    const int tid  = threadIdx.x;
    const int lane = tid & 31;
    const int wid  = tid >> 5;
    const int wm = wid >> 2, wn = wid & 3, grp = lane >> 2, qp = lane & 3;
    const int n0 = blockIdx.x * 64;
    const int m0 = blockIdx.z * 64;
    float acc[2][2][4] = {};
    hmma_tile(A + (size_t)m0*ldA, ldA, W + (size_t)n0*ldW, ldW, &sm, acc, K);
    #pragma unroll
    for (int mf = 0; mf < 2; mf++)
        #pragma unroll
        for (int nf = 0; nf < 2; nf++)
            #pragma unroll
            for (int q = 0; q < 4; q++) {
                int m = m0 + 32*wm + 16*mf + grp + (q >> 1)*8;
                int n = n0 + 16*wn + 8*nf + 2*qp + (q & 1);
                float v = acc[mf][nf][q] + bias[n];
                if (mode == 3) {
                    g_att1h[(size_t)m*A_DIM + n] = __float2half(v);
                } else {
                    if (n < H) g_h0[(size_t)m*H + n] = v;
                    else       g_c [(size_t)m*H + n - H] = v;
                }
            }
}

// ---------------- persistent decode loop ---------------------------------------
__device__ __forceinline__ void gbar(int nblk, int& target)
{
    __syncthreads();
    target += nblk;
    if (threadIdx.x == 0) {
        __threadfence();
        atomicAdd((unsigned*)&g_bar, 1u);
        while (g_bar < (unsigned)target) { }
        __threadfence();
    }
    __syncthreads();
}

__global__ void __launch_bounds__(256, 2) k_decode(
    const int*   __restrict__ lengths,
    const float* __restrict__ attw,
    const float* __restrict__ attb,
    const float* __restrict__ cls_b,
    float* __restrict__ outy,
    float* __restrict__ outa)
{
    __shared__ SmemT sm;
    __shared__ float sred[256];
    __shared__ float sal[256];
    const int nblk = gridDim.x;
    const int bid  = blockIdx.x;
    const int tid  = threadIdx.x;
    const int lane = tid & 31;
    const int wid  = tid >> 5;
    const int wm = wid >> 2, wn = wid & 3, grp = lane >> 2, qp = lane & 3;
    int target = 0;

    for (int t = 0; t < T; t++) {
        // ---- Phase A: att2|gate small GEMM (tiles 0..39) + cls(t-1) (tiles 40..196)
        const int ntA = (t > 0) ? 197 : 40;
        for (int tile = bid; tile < ntA; tile += nblk) {
            float acc[2][2][4] = {};
            if (tile < 40) {
                const int n0 = tile * 64;
                hmma_tile(g_xhh + (E + D), XH, g_smallw + (size_t)n0*H, H, &sm, acc, H);
                #pragma unroll
                for (int mf = 0; mf < 2; mf++)
                    #pragma unroll
                    for (int nf = 0; nf < 2; nf++)
                        #pragma unroll
                        for (int q = 0; q < 4; q++) {
                            int m = 32*wm + 16*mf + grp + (q >> 1)*8;
                            int n = n0 + 16*wn + 8*nf + 2*qp + (q & 1);
                            float v = acc[mf][nf][q] + g_smallb[n];
                            if (n >= A_DIM) v = 1.f / (1.f + expf(-v));
                            g_small_out[(size_t)m*NSMALL + n] = v;
                        }
            } else {
                const int n0 = (tile - 40) * 64;
                hmma_tile(g_xhh + (E + D), XH, g_clswh + (size_t)n0*H, H, &sm, acc, H);
                const int tp = t - 1;
                #pragma unroll
                for (int mf = 0; mf < 2; mf++)
                    #pragma unroll
                    for (int nf = 0; nf < 2; nf++)
                        #pragma unroll
                        for (int q = 0; q < 4; q++) {
                            int m = 32*wm + 16*mf + grp + (q >> 1)*8;
                            int n = n0 + 16*wn + 8*nf + 2*qp + (q & 1);
                            if (n < V) {
                                int act = tp < (lengths[m] - 1);
                                outy[(size_t)m*T*V + (size_t)tp*V + n] =
                                    act ? (acc[mf][nf][q] + cls_b[n]) : 0.f;
                            }
                        }
            }
        }
        gbar(nblk, target);

        // ---- Phase B (fused): e -> softmax -> awe, one block per batch b
        for (int b = bid; b < B; b += nblk) {
            const float* a2 = g_small_out + (size_t)b * NSMALL;
            // e scores: warp w handles p = w, w+8, ...
            for (int p = wid; p < P; p += 8) {
                const __half* a1 = g_att1h + (size_t)(b*P + p) * A_DIM;
                float s = 0.f;
                #pragma unroll 4
                for (int a = lane; a < A_DIM; a += 32) {
                    float v = __half2float(a1[a]) + a2[a];
                    if (v > 0.f) s += v * attw[a];
                }
                #pragma unroll
                for (int o = 16; o; o >>= 1) s += __shfl_xor_sync(0xffffffffu, s, o);
                if (lane == 0) sal[p] = s + attb[0];
            }
            __syncthreads();
            // softmax over sal[0..195]
            float ev = (tid < P) ? sal[tid] : -1e30f;
            sred[tid] = ev; __syncthreads();
            for (int s2 = 128; s2 > 0; s2 >>= 1) {
                if (tid < s2) sred[tid] = fmaxf(sred[tid], sred[tid + s2]);
                __syncthreads();
            }
            float mx = sred[0]; __syncthreads();
            float ex = (tid < P) ? expf(ev - mx) : 0.f;
            sred[tid] = ex; __syncthreads();
            for (int s2 = 128; s2 > 0; s2 >>= 1) {
                if (tid < s2) sred[tid] += sred[tid + s2];
                __syncthreads();
            }
            float inv = 1.f / sred[0];
            __syncthreads();
            if (tid < P) sal[tid] = ex * inv;
            __syncthreads();
            // awe: thread tid covers half2 columns tid, tid+256, tid+512, tid+768
            const __half2* fb = (const __half2*)g_featsh + (size_t)b*P*(D/2) + tid;
            float2 acc2[4] = {};
            for (int p = 0; p < P; p++) {
                const __half2* row = fb + (size_t)p*(D/2);
                float s = sal[p];
                #pragma unroll
                for (int c2 = 0; c2 < 4; c2++) {
                    float2 f = __half22float2(row[c2*256]);
                    acc2[c2].x += s * f.x;
                    acc2[c2].y += s * f.y;
                }
            }
            #pragma unroll
            for (int c2 = 0; c2 < 4; c2++) {
                const int d = 2*(tid + c2*256);
                acc2[c2].x *= a2[A_DIM + d];
                acc2[c2].y *= a2[A_DIM + d + 1];
                *(__half2*)&g_xhh[(size_t)b*XH + E + d] = __floats2half2_rn(acc2[c2].x, acc2[c2].y);
            }
            if (tid < P) {
                int act = t < (lengths[b] - 1);
                outa[((size_t)b*T + t)*P + tid] = act ? sal[tid] : 0.f;
            }
            __syncthreads();
        }
        gbar(nblk, target);

        // ---- Phase C: gates GEMM, 32 n-tiles x 4 K-splits
        for (int tile = bid; tile < 32*KSPLIT; tile += nblk) {
            const int n0 = (tile & 31) * 64;
            const int ks = tile >> 5;
            float acc[2][2][4] = {};
            hmma_tile(g_xhh + ks*KS_LEN, XH,
                      g_Wcath + (size_t)n0*XH + ks*KS_LEN, XH, &sm, acc, KS_LEN);
            #pragma unroll
            for (int mf = 0; mf < 2; mf++)
                #pragma unroll
                for (int nf = 0; nf < 2; nf++)
                    #pragma unroll
                    for (int q = 0; q < 4; q++) {
                        int m = 32*wm + 16*mf + grp + (q >> 1)*8;
                        int n = n0 + 16*wn + 8*nf + 2*qp + (q & 1);
                        g_gparts[(size_t)ks*B*G4 + (size_t)m*G4 + n] = acc[mf][nf][q];
                    }
        }
        gbar(nblk, target);

        // ---- Phase D: LSTM pointwise + next-step state staging
        for (int i = bid*256 + tid; i < B*H; i += nblk*256) {
            const int b = i >> 9, j = i & (H-1);
            float gi = g_bcat[j], gf = g_bcat[j + H], gg = g_bcat[j + 2*H], go = g_bcat[j + 3*H];
            #pragma unroll
            for (int s = 0; s < KSPLIT; s++) {
                const float* pp = g_gparts + (size_t)s*B*G4 + (size_t)b*G4;
                gi += pp[j]; gf += pp[j + H]; gg += pp[j + 2*H]; go += pp[j + 3*H];
            }
            float si = 1.f / (1.f + expf(-gi));
            float sf = 1.f / (1.f + expf(-gf));
            float so = 1.f / (1.f + expf(-go));
            float c2 = sf * g_c[i] + si * tanhf(gg);
            float h2 = so * tanhf(c2);
            g_c[i] = c2;
            g_xhh[(size_t)b*XH + E + D + j] = __float2half(h2);
            if (t + 1 < T) g_xhh[(size_t)b*XH + j] = g_embh[(size_t)(b*T + (t+1))*E + j];
        }
        gbar(nblk, target);
    }

    // ---- final cls for t = T-1
    for (int tile = bid; tile < 157; tile += nblk) {
        const int n0 = tile * 64;
        float acc[2][2][4] = {};
        hmma_tile(g_xhh + (E + D), XH, g_clswh + (size_t)n0*H, H, &sm, acc, H);
        const int tp = T - 1;
        #pragma unroll
        for (int mf = 0; mf < 2; mf++)
            #pragma unroll
            for (int nf = 0; nf < 2; nf++)
                #pragma unroll
                for (int q = 0; q < 4; q++) {
                    int m = 32*wm + 16*mf + grp + (q >> 1)*8;
                    int n = n0 + 16*wn + 8*nf + 2*qp + (q & 1);
                    if (n < V) {
                        int act = tp < (lengths[m] - 1);
                        outy[(size_t)m*T*V + (size_t)tp*V + n] =
                            act ? (acc[mf][nf][q] + cls_b[n]) : 0.f;
                    }
                }
    }
}

// ---------------- host driver ---------------------------------------------------
extern "C" void kernel_launch(void* const* d_in, const int* in_sizes, int n_in,
                              void* d_out, int out_size)
{
    const float* features = (const float*)d_in[0];
    const int*   captions = (const int*)  d_in[1];
    const int*   lengths  = (const int*)  d_in[2];
    const float* emb      = (const float*)d_in[3];
    const float* W_ih     = (const float*)d_in[4];
    const float* b_ih     = (const float*)d_in[5];
    const float* W_hh     = (const float*)d_in[6];
    const float* b_hh     = (const float*)d_in[7];
    const float* h_fc_w   = (const float*)d_in[8];
    const float* h_fc_b   = (const float*)d_in[9];
    const float* c_fc_w   = (const float*)d_in[10];
    const float* c_fc_b   = (const float*)d_in[11];
    const float* f_beta_w = (const float*)d_in[12];
    const float* f_beta_b = (const float*)d_in[13];
    const float* cls_w    = (const float*)d_in[14];
    const float* cls_b    = (const float*)d_in[15];
    const float* enc_w    = (const float*)d_in[16];
    const float* enc_b    = (const float*)d_in[17];
    const float* dec_w    = (const float*)d_in[18];
    const float* dec_b    = (const float*)d_in[19];
    const float* att_w    = (const float*)d_in[20];
    const float* att_b    = (const float*)d_in[21];

    float* outy = (float*)d_out;
    float* outa = outy + (size_t)B*T*V;

    __half *p_featsh, *p_encwh, *p_meanfh, *p_hcwh;
    float  *p_hcb;
    cudaGetSymbolAddress((void**)&p_featsh, g_featsh);
    cudaGetSymbolAddress((void**)&p_encwh,  g_encwh);
    cudaGetSymbolAddress((void**)&p_meanfh, g_meanfh);
    cudaGetSymbolAddress((void**)&p_hcwh,   g_hcwh);
    cudaGetSymbolAddress((void**)&p_hcb,    g_hcb);

    int nsm = 148;
    cudaDeviceGetAttribute(&nsm, cudaDevAttrMultiProcessorCount, 0);

    k_zero    <<<1, 32>>>();
    k_f2h_mean<<<(B*D + 255)/256, 256>>>(features);
    k_ench    <<<(A_DIM*D/4 + 255)/256, 256>>>(enc_w);
    k_wcath   <<<dim3(3, G4), 256>>>(W_ih, b_ih, W_hh, b_hh);
    k_clsh    <<<VPAD, 128>>>(cls_w);
    k_hgemm   <<<dim3(A_DIM/64, 1, (B*P)/64), 256>>>(p_featsh, D, p_encwh, D, enc_b, D, 3);
    k_embh    <<<(B*T*E + 255)/256, 256>>>(emb, captions);
    k_smallwh <<<NSMALL, 128>>>(dec_w, dec_b, f_beta_w, f_beta_b);
    k_hcwh    <<<2*H, 256>>>(h_fc_w, h_fc_b, c_fc_w, c_fc_b);
    k_hgemm   <<<dim3(2*H/64, 1, 1), 256>>>(p_meanfh, D, p_hcwh, D, p_hcb, D, 4);
    k_initxh  <<<(B*H + 255)/256, 256>>>();
    k_decode  <<<2*nsm, 256>>>(lengths, att_w, att_b, cls_b, outy, outa);
}

// round 6
// speedup vs baseline: 1.7365x; 1.6990x over previous
#include <cuda_runtime.h>
#include <cuda_fp16.h>
#include <math.h>

#define B     64
#define P     196
#define D     2048
#define A_DIM 512
#define H     512
#define E     512
#define V     10000
#define VPAD  10048
#define T     19
#define LCAP  20
#define XH    3072
#define G4    2048
#define NSMALL 2560
#define GP_SLOTS 6     /* 0:emb 1:h 2..5: awe split-4 */

// ---------------- device scratch ---------------------------------------------
__device__ __half g_featsh[(size_t)B*P*D];
__device__ __half g_att1h[(size_t)B*P*A_DIM];
__device__ __half g_Wcath[(size_t)G4*XH];
__device__ __half g_clswh[(size_t)VPAD*H];
__device__ __half g_encwh[(size_t)A_DIM*D];
__device__ __half g_smallw[(size_t)NSMALL*H];
__device__ __half g_hcwh[(size_t)2*H*D];
__device__ __half g_meanfh[B*D];
__device__ __half g_embh[(size_t)B*T*E];
__device__ __half g_xhh[(size_t)B*XH];
__device__ float  g_small_out[(size_t)B*NSMALL];
__device__ float  g_smallb[NSMALL];
__device__ float  g_hcb[2*H];
__device__ float  g_bcat[G4];
__device__ float  g_h0[B*H];
__device__ float  g_c[B*H];
__device__ float  g_e[B*P];
__device__ float  g_gparts[(size_t)GP_SLOTS*B*G4];
__device__ volatile unsigned g_bar;

__device__ __forceinline__ void st_half4(__half* dst, float4 v)
{
    ((__half2*)dst)[0] = __floats2half2_rn(v.x, v.y);
    ((__half2*)dst)[1] = __floats2half2_rn(v.z, v.w);
}

__global__ void k_zero() { if (threadIdx.x == 0) *(unsigned*)&g_bar = 0u; }

// ---------------- preproc mega-kernel (elementwise, region dispatch) ----------
#define R0 131072     /* f2h + mean  : B*D            */
#define R1 262144     /* ench        : A*D/4          */
#define R2 1572864    /* wcath       : G4*XH/4        */
#define R3 1286144    /* clsh        : VPAD*H/4       */
#define R4 327680     /* smallwh     : NSMALL*H/4     */
#define R5 524288     /* hcwh        : 2H*D/4         */
#define R6 155648     /* embh        : B*T*E/4        */
#define R7 2560       /* biases                       */
#define N_ELEM (R0+R1+R2+R3+R4+R5+R6+R7)   /* 4262400 = 16650*256 */

__global__ void k_prep_elem(
    const float* __restrict__ f,     const float* __restrict__ enc_w,
    const float* __restrict__ W_ih,  const float* __restrict__ b_ih,
    const float* __restrict__ W_hh,  const float* __restrict__ b_hh,
    const float* __restrict__ cls_w,
    const float* __restrict__ dec_w, const float* __restrict__ dec_b,
    const float* __restrict__ fb_w,  const float* __restrict__ fb_b,
    const float* __restrict__ h_fc_w,const float* __restrict__ h_fc_b,
    const float* __restrict__ c_fc_w,const float* __restrict__ c_fc_b,
    const float* __restrict__ emb,   const int* __restrict__ captions)
{
    int idx = blockIdx.x * 256 + threadIdx.x;

    if (idx < R0) {                                  // features fp16 + mean
        int b = idx >> 11, d = idx & (D-1);
        const float* p = f + (size_t)b*P*D + d;
        __half* o = g_featsh + (size_t)b*P*D + d;
        float s = 0.f;
        #pragma unroll 4
        for (int q = 0; q < P; q++) {
            float v = p[(size_t)q*D];
            s += v;
            o[(size_t)q*D] = __float2half(v);
        }
        g_meanfh[idx] = __float2half(s * (1.f/196.f));
        return;
    }
    idx -= R0;
    if (idx < R1) {                                  // enc_w fp16
        size_t i = (size_t)idx * 4;
        st_half4(g_encwh + i, *(const float4*)(enc_w + i));
        return;
    }
    idx -= R1;
    if (idx < R2) {                                  // Wcat fp16
        int j = idx / (XH/4);
        int k = (idx % (XH/4)) * 4;
        float4 v = (k < E + D) ? *(const float4*)(W_ih + (size_t)j*(E+D) + k)
                               : *(const float4*)(W_hh + (size_t)j*H + (k - (E+D)));
        st_half4(g_Wcath + (size_t)j*XH + k, v);
        return;
    }
    idx -= R2;
    if (idx < R3) {                                  // cls_w fp16 (padded)
        int n = idx >> 7, k = (idx & 127) * 4;
        float4 v = make_float4(0.f,0.f,0.f,0.f);
        if (n < V) v = *(const float4*)(cls_w + (size_t)n*H + k);
        st_half4(g_clswh + (size_t)n*H + k, v);
        return;
    }
    idx -= R3;
    if (idx < R4) {                                  // [dec_w|f_beta_w] fp16
        int n = idx >> 7, k = (idx & 127) * 4;
        const float* src = (n < A_DIM) ? dec_w + (size_t)n*H : fb_w + (size_t)(n - A_DIM)*H;
        st_half4(g_smallw + (size_t)n*H + k, *(const float4*)(src + k));
        return;
    }
    idx -= R4;
    if (idx < R5) {                                  // [h_fc_w|c_fc_w] fp16
        int n = idx >> 9, k = (idx & 511) * 4;
        const float* src = (n < H) ? h_fc_w + (size_t)n*D : c_fc_w + (size_t)(n - H)*D;
        st_half4(g_hcwh + (size_t)n*D + k, *(const float4*)(src + k));
        return;
    }
    idx -= R5;
    if (idx < R6) {                                  // embeddings fp16
        int row = idx >> 7, e4 = (idx & 127) * 4;
        int b = row / T, t = row % T;
        int tok = captions[b*LCAP + t];
        st_half4(g_embh + (size_t)row*E + e4, *(const float4*)(emb + (size_t)tok*E + e4));
        return;
    }
    idx -= R6;
    if (idx < R7) {                                  // biases
        if (idx < G4)  g_bcat[idx]   = b_ih[idx] + b_hh[idx];
        g_smallb[idx] = (idx < A_DIM) ? dec_b[idx] : fb_b[idx - A_DIM];
        if (idx < 2*H) g_hcb[idx]    = (idx < H) ? h_fc_b[idx] : c_fc_b[idx - H];
    }
}

// ---------------- HMMA core ----------------------------------------------------
__device__ __forceinline__ void mma16816(float c[4], const unsigned a[4], const unsigned b[2])
{
    asm volatile(
        "mma.sync.aligned.m16n8k16.row.col.f32.f16.f16.f32 "
        "{%0,%1,%2,%3}, {%4,%5,%6,%7}, {%8,%9}, {%0,%1,%2,%3};"
        : "+f"(c[0]), "+f"(c[1]), "+f"(c[2]), "+f"(c[3])
        : "r"(a[0]), "r"(a[1]), "r"(a[2]), "r"(a[3]), "r"(b[0]), "r"(b[1]));
}

struct SmemT { __half As[64][40]; __half Ws[64][40]; };

__device__ __forceinline__ void hmma_tile(
    const __half* __restrict__ Aptr, int ldA,
    const __half* __restrict__ Wptr, int ldW,
    SmemT* sm, float acc[2][2][4], int K)
{
    const int tid  = threadIdx.x;
    const int lane = tid & 31;
    const int wid  = tid >> 5;
    const int wm   = wid >> 2;
    const int wn   = wid & 3;
    const int grp  = lane >> 2;
    const int qp   = lane & 3;
    const int lrow = tid >> 2;
    const int lcol = (tid & 3) * 8;

    const __half* ap = Aptr + (size_t)lrow*ldA + lcol;
    const __half* wp = Wptr + (size_t)lrow*ldW + lcol;

    uint4 av = *(const uint4*)ap;
    uint4 wv = *(const uint4*)wp;

    for (int kc = 0; kc < K; kc += 32) {
        __syncthreads();
        *(uint4*)&sm->As[lrow][lcol] = av;
        *(uint4*)&sm->Ws[lrow][lcol] = wv;
        __syncthreads();
        if (kc + 32 < K) {
            av = *(const uint4*)(ap + kc + 32);
            wv = *(const uint4*)(wp + kc + 32);
        }
        #pragma unroll
        for (int ks = 0; ks < 2; ks++) {
            const int kb = 16*ks + 2*qp;
            unsigned afr[2][4], bfr[2][2];
            #pragma unroll
            for (int mf = 0; mf < 2; mf++) {
                const int r = 32*wm + 16*mf + grp;
                afr[mf][0] = *(const unsigned*)&sm->As[r    ][kb    ];
                afr[mf][1] = *(const unsigned*)&sm->As[r + 8][kb    ];
                afr[mf][2] = *(const unsigned*)&sm->As[r    ][kb + 8];
                afr[mf][3] = *(const unsigned*)&sm->As[r + 8][kb + 8];
            }
            #pragma unroll
            for (int nf = 0; nf < 2; nf++) {
                const int r = 16*wn + 8*nf + grp;
                bfr[nf][0] = *(const unsigned*)&sm->Ws[r][kb    ];
                bfr[nf][1] = *(const unsigned*)&sm->Ws[r][kb + 8];
            }
            #pragma unroll
            for (int mf = 0; mf < 2; mf++)
                #pragma unroll
                for (int nf = 0; nf < 2; nf++)
                    mma16816(acc[mf][nf], afr[mf], bfr[nf]);
        }
    }
}

// ---------------- preproc GEMMs: att1 (tiles 0..1567) + h0/c0 (1568..1583) ----
__global__ void __launch_bounds__(256, 2) k_prep_gemm(const float* __restrict__ enc_b)
{
    __shared__ SmemT sm;
    const int tid  = threadIdx.x;
    const int lane = tid & 31;
    const int wid  = tid >> 5;
    const int wm = wid >> 2, wn = wid & 3, grp = lane >> 2, qp = lane & 3;
    const int tile = blockIdx.x;
    float acc[2][2][4] = {};

    if (tile < 1568) {                       // att1
        const int m0 = (tile >> 3) * 64;
        const int n0 = (tile & 7) * 64;
        hmma_tile(g_featsh + (size_t)m0*D, D, g_encwh + (size_t)n0*D, D, &sm, acc, D);
        #pragma unroll
        for (int mf = 0; mf < 2; mf++)
            #pragma unroll
            for (int nf = 0; nf < 2; nf++)
                #pragma unroll
                for (int q = 0; q < 4; q++) {
                    int m = m0 + 32*wm + 16*mf + grp + (q >> 1)*8;
                    int n = n0 + 16*wn + 8*nf + 2*qp + (q & 1);
                    g_att1h[(size_t)m*A_DIM + n] = __float2half(acc[mf][nf][q] + enc_b[n]);
                }
    } else {                                 // h0 / c0
        const int n0 = (tile - 1568) * 64;
        hmma_tile(g_meanfh, D, g_hcwh + (size_t)n0*D, D, &sm, acc, D);
        #pragma unroll
        for (int mf = 0; mf < 2; mf++)
            #pragma unroll
            for (int nf = 0; nf < 2; nf++)
                #pragma unroll
                for (int q = 0; q < 4; q++) {
                    int m = 32*wm + 16*mf + grp + (q >> 1)*8;
                    int n = n0 + 16*wn + 8*nf + 2*qp + (q & 1);
                    float v = acc[mf][nf][q] + g_hcb[n];
                    if (n < H) g_h0[(size_t)m*H + n] = v;
                    else       g_c [(size_t)m*H + n - H] = v;
                }
    }
}

// ---------------- grid barrier with HW-sleep backoff ---------------------------
__device__ __forceinline__ void gbar(int nblk, int& target)
{
    __syncthreads();
    target += nblk;
    if (threadIdx.x == 0) {
        __threadfence();                      // release
        atomicAdd((unsigned*)&g_bar, 1u);
        while (g_bar < (unsigned)target)
            __nanosleep(128);
        __threadfence();                      // acquire (invalidates L1)
    }
    __syncthreads();
}

// ---------------- persistent decode --------------------------------------------
__global__ void __launch_bounds__(256, 2) k_decode(
    const int*   __restrict__ lengths,
    const float* __restrict__ attw,
    const float* __restrict__ attb,
    const float* __restrict__ cls_b,
    float* __restrict__ outy,
    float* __restrict__ outa)
{
    __shared__ SmemT sm;
    __shared__ float sred[256];
    __shared__ float sal[256];
    const int nblk = gridDim.x;
    const int bid  = blockIdx.x;
    const int tid  = threadIdx.x;
    const int lane = tid & 31;
    const int wid  = tid >> 5;
    const int wm = wid >> 2, wn = wid & 3, grp = lane >> 2, qp = lane & 3;
    int target = 0;

    // ---- init: xhh = [emb(t=0) | - | h0]
    for (int i = bid*256 + tid; i < B*H; i += nblk*256) {
        const int b = i >> 9, j = i & (H-1);
        g_xhh[(size_t)b*XH + j]         = g_embh[(size_t)(b*T)*E + j];
        g_xhh[(size_t)b*XH + E + D + j] = __float2half(g_h0[i]);
    }
    gbar(nblk, target);

    for (int t = 0; t < T; t++) {
        // ==== Phase A: small GEMM (0..39) + gates emb|h partial (40..103) + cls(t-1) (104..260)
        const int ntA = (t > 0) ? 261 : 104;
        for (int tile = bid; tile < ntA; tile += nblk) {
            float acc[2][2][4] = {};
            if (tile < 40) {
                const int n0 = tile * 64;
                hmma_tile(g_xhh + (E + D), XH, g_smallw + (size_t)n0*H, H, &sm, acc, H);
                #pragma unroll
                for (int mf = 0; mf < 2; mf++)
                    #pragma unroll
                    for (int nf = 0; nf < 2; nf++)
                        #pragma unroll
                        for (int q = 0; q < 4; q++) {
                            int m = 32*wm + 16*mf + grp + (q >> 1)*8;
                            int n = n0 + 16*wn + 8*nf + 2*qp + (q & 1);
                            float v = acc[mf][nf][q] + g_smallb[n];
                            if (n >= A_DIM) v = 1.f / (1.f + expf(-v));
                            g_small_out[(size_t)m*NSMALL + n] = v;
                        }
            } else if (tile < 104) {
                const int it = tile - 40;
                const int n0 = (it & 31) * 64;
                const int part = it >> 5;              // 0: emb cols, 1: h cols
                const int koff = part ? (E + D) : 0;
                hmma_tile(g_xhh + koff, XH, g_Wcath + (size_t)n0*XH + koff, XH, &sm, acc, H);
                #pragma unroll
                for (int mf = 0; mf < 2; mf++)
                    #pragma unroll
                    for (int nf = 0; nf < 2; nf++)
                        #pragma unroll
                        for (int q = 0; q < 4; q++) {
                            int m = 32*wm + 16*mf + grp + (q >> 1)*8;
                            int n = n0 + 16*wn + 8*nf + 2*qp + (q & 1);
                            g_gparts[(size_t)part*B*G4 + (size_t)m*G4 + n] = acc[mf][nf][q];
                        }
            } else {
                const int n0 = (tile - 104) * 64;
                hmma_tile(g_xhh + (E + D), XH, g_clswh + (size_t)n0*H, H, &sm, acc, H);
                const int tp = t - 1;
                #pragma unroll
                for (int mf = 0; mf < 2; mf++)
                    #pragma unroll
                    for (int nf = 0; nf < 2; nf++)
                        #pragma unroll
                        for (int q = 0; q < 4; q++) {
                            int m = 32*wm + 16*mf + grp + (q >> 1)*8;
                            int n = n0 + 16*wn + 8*nf + 2*qp + (q & 1);
                            if (n < V) {
                                int act = tp < (lengths[m] - 1);
                                outy[(size_t)m*T*V + (size_t)tp*V + n] =
                                    act ? (acc[mf][nf][q] + cls_b[n]) : 0.f;
                            }
                        }
            }
        }
        gbar(nblk, target);

        // ==== Phase B1: e scores (all blocks, one warp per (b,p))
        for (int idx = bid*8 + wid; idx < B*P; idx += nblk*8) {
            const int b = idx / P;
            const __half2* a1 = (const __half2*)(g_att1h + (size_t)idx * A_DIM);
            const float2*  a2 = (const float2*)(g_small_out + (size_t)b * NSMALL);
            const float2*  aw = (const float2*)attw;
            float s = 0.f;
            #pragma unroll
            for (int a = lane; a < A_DIM/2; a += 32) {
                float2 v1 = __half22float2(a1[a]);
                float2 v2 = a2[a];
                float2 w2 = aw[a];
                float x = v1.x + v2.x, y = v1.y + v2.y;
                if (x > 0.f) s += x * w2.x;
                if (y > 0.f) s += y * w2.y;
            }
            #pragma unroll
            for (int o = 16; o; o >>= 1) s += __shfl_xor_sync(0xffffffffu, s, o);
            if (lane == 0) g_e[idx] = s + attb[0];
        }
        gbar(nblk, target);

        // ==== Phase B2: softmax + awe (256 tiles = (b, chunk of 512))
        for (int tile = bid; tile < B*4; tile += nblk) {
            const int b = tile >> 2, chunk = tile & 3;
            float ev = (tid < P) ? g_e[b*P + tid] : -1e30f;
            sred[tid] = ev; __syncthreads();
            for (int s2 = 128; s2 > 0; s2 >>= 1) {
                if (tid < s2) sred[tid] = fmaxf(sred[tid], sred[tid + s2]);
                __syncthreads();
            }
            float mx = sred[0]; __syncthreads();
            float ex = (tid < P) ? expf(ev - mx) : 0.f;
            sred[tid] = ex; __syncthreads();
            for (int s2 = 128; s2 > 0; s2 >>= 1) {
                if (tid < s2) sred[tid] += sred[tid + s2];
                __syncthreads();
            }
            float inv = 1.f / sred[0];
            __syncthreads();
            if (tid < P) sal[tid] = ex * inv;
            __syncthreads();

            const __half2* fb = (const __half2*)g_featsh + (size_t)b*P*(D/2) + chunk*256 + tid;
            float2 acc2 = make_float2(0.f, 0.f);
            #pragma unroll 4
            for (int p = 0; p < P; p++) {
                float2 fv = __half22float2(fb[(size_t)p*(D/2)]);
                acc2.x += sal[p] * fv.x;
                acc2.y += sal[p] * fv.y;
            }
            const int d = chunk*512 + 2*tid;
            acc2.x *= g_small_out[(size_t)b*NSMALL + A_DIM + d];
            acc2.y *= g_small_out[(size_t)b*NSMALL + A_DIM + d + 1];
            *(__half2*)&g_xhh[(size_t)b*XH + E + d] = __floats2half2_rn(acc2.x, acc2.y);

            if (chunk == 0 && tid < P) {
                int act = t < (lengths[b] - 1);
                outa[((size_t)b*T + t)*P + tid] = act ? sal[tid] : 0.f;
            }
            __syncthreads();
        }
        gbar(nblk, target);

        // ==== Phase C: gates awe-part, 32 n-tiles x split-4 over K=2048
        for (int tile = bid; tile < 128; tile += nblk) {
            const int n0 = (tile & 31) * 64;
            const int ks = tile >> 5;
            const int koff = E + ks*512;
            float acc[2][2][4] = {};
            hmma_tile(g_xhh + koff, XH, g_Wcath + (size_t)n0*XH + koff, XH, &sm, acc, 512);
            #pragma unroll
            for (int mf = 0; mf < 2; mf++)
                #pragma unroll
                for (int nf = 0; nf < 2; nf++)
                    #pragma unroll
                    for (int q = 0; q < 4; q++) {
                        int m = 32*wm + 16*mf + grp + (q >> 1)*8;
                        int n = n0 + 16*wn + 8*nf + 2*qp + (q & 1);
                        g_gparts[(size_t)(2 + ks)*B*G4 + (size_t)m*G4 + n] = acc[mf][nf][q];
                    }
        }
        gbar(nblk, target);

        // ==== Phase D: LSTM pointwise + stage next emb
        for (int i = bid*256 + tid; i < B*H; i += nblk*256) {
            const int b = i >> 9, j = i & (H-1);
            float gi = g_bcat[j], gf = g_bcat[j + H], gg = g_bcat[j + 2*H], go = g_bcat[j + 3*H];
            #pragma unroll
            for (int s = 0; s < GP_SLOTS; s++) {
                const float* pp = g_gparts + (size_t)s*B*G4 + (size_t)b*G4;
                gi += pp[j]; gf += pp[j + H]; gg += pp[j + 2*H]; go += pp[j + 3*H];
            }
            float si = 1.f / (1.f + expf(-gi));
            float sf = 1.f / (1.f + expf(-gf));
            float so = 1.f / (1.f + expf(-go));
            float c2 = sf * g_c[i] + si * tanhf(gg);
            float h2 = so * tanhf(c2);
            g_c[i] = c2;
            g_xhh[(size_t)b*XH + E + D + j] = __float2half(h2);
            if (t + 1 < T) g_xhh[(size_t)b*XH + j] = g_embh[(size_t)(b*T + (t+1))*E + j];
        }
        gbar(nblk, target);
    }

    // ---- final cls (t = T-1)
    for (int tile = bid; tile < 157; tile += nblk) {
        const int n0 = tile * 64;
        float acc[2][2][4] = {};
        hmma_tile(g_xhh + (E + D), XH, g_clswh + (size_t)n0*H, H, &sm, acc, H);
        const int tp = T - 1;
        #pragma unroll
        for (int mf = 0; mf < 2; mf++)
            #pragma unroll
            for (int nf = 0; nf < 2; nf++)
                #pragma unroll
                for (int q = 0; q < 4; q++) {
                    int m = 32*wm + 16*mf + grp + (q >> 1)*8;
                    int n = n0 + 16*wn + 8*nf + 2*qp + (q & 1);
                    if (n < V) {
                        int act = tp < (lengths[m] - 1);
                        outy[(size_t)m*T*V + (size_t)tp*V + n] =
                            act ? (acc[mf][nf][q] + cls_b[n]) : 0.f;
                    }
                }
    }
}

// ---------------- host driver ---------------------------------------------------
extern "C" void kernel_launch(void* const* d_in, const int* in_sizes, int n_in,
                              void* d_out, int out_size)
{
    const float* features = (const float*)d_in[0];
    const int*   captions = (const int*)  d_in[1];
    const int*   lengths  = (const int*)  d_in[2];
    const float* emb      = (const float*)d_in[3];
    const float* W_ih     = (const float*)d_in[4];
    const float* b_ih     = (const float*)d_in[5];
    const float* W_hh     = (const float*)d_in[6];
    const float* b_hh     = (const float*)d_in[7];
    const float* h_fc_w   = (const float*)d_in[8];
    const float* h_fc_b   = (const float*)d_in[9];
    const float* c_fc_w   = (const float*)d_in[10];
    const float* c_fc_b   = (const float*)d_in[11];
    const float* f_beta_w = (const float*)d_in[12];
    const float* f_beta_b = (const float*)d_in[13];
    const float* cls_w    = (const float*)d_in[14];
    const float* cls_b    = (const float*)d_in[15];
    const float* enc_w    = (const float*)d_in[16];
    const float* enc_b    = (const float*)d_in[17];
    const float* dec_w    = (const float*)d_in[18];
    const float* dec_b    = (const float*)d_in[19];
    const float* att_w    = (const float*)d_in[20];
    const float* att_b    = (const float*)d_in[21];

    float* outy = (float*)d_out;
    float* outa = outy + (size_t)B*T*V;

    int nsm = 148;
    cudaDeviceGetAttribute(&nsm, cudaDevAttrMultiProcessorCount, 0);

    k_zero     <<<1, 32>>>();
    k_prep_elem<<<N_ELEM/256, 256>>>(features, enc_w, W_ih, b_ih, W_hh, b_hh, cls_w,
                                     dec_w, dec_b, f_beta_w, f_beta_b,
                                     h_fc_w, h_fc_b, c_fc_w, c_fc_b, emb, captions);
    k_prep_gemm<<<1584, 256>>>(enc_b);
    k_decode   <<<2*nsm, 256>>>(lengths, att_w, att_b, cls_b, outy, outa);
}

// round 7
// speedup vs baseline: 2.4980x; 1.4385x over previous
#include <cuda_runtime.h>
#include <cuda_fp16.h>
#include <math.h>

#define B     64
#define P     196
#define D     2048
#define A_DIM 512
#define H     512
#define E     512
#define V     10000
#define VPAD  10048
#define T     19
#define LCAP  20
#define XH    3072
#define G4    2048
#define NSMALL 2560
#define GP_SLOTS 6     /* 0:emb 1:h 2..5: awe split-4 */
#define STAGES 3

// ---------------- device scratch ---------------------------------------------
__device__ __half g_featsh[(size_t)B*P*D];
__device__ __half g_att1h[(size_t)B*P*A_DIM];
__device__ __half g_Wcath[(size_t)G4*XH];
__device__ __half g_clswh[(size_t)VPAD*H];
__device__ __half g_encwh[(size_t)A_DIM*D];
__device__ __half g_smallw[(size_t)NSMALL*H];
__device__ __half g_hcwh[(size_t)2*H*D];
__device__ __half g_meanfh[B*D];
__device__ __half g_embh[(size_t)B*T*E];
__device__ __half g_xhh[(size_t)B*XH];
__device__ float  g_small_out[(size_t)B*NSMALL];
__device__ float  g_smallb[NSMALL];
__device__ float  g_hcb[2*H];
__device__ float  g_bcat[G4];
__device__ float  g_h0[B*H];
__device__ float  g_c[B*H];
__device__ float  g_e[B*P];
__device__ float  g_gparts[(size_t)GP_SLOTS*B*G4];
__device__ volatile unsigned g_bar;

__device__ __forceinline__ void st_half4(__half* dst, float4 v)
{
    ((__half2*)dst)[0] = __floats2half2_rn(v.x, v.y);
    ((__half2*)dst)[1] = __floats2half2_rn(v.z, v.w);
}

// ---------------- cp.async helpers --------------------------------------------
__device__ __forceinline__ void cp16(void* smem, const void* gmem)
{
    unsigned sa = (unsigned)__cvta_generic_to_shared(smem);
    asm volatile("cp.async.cg.shared.global [%0], [%1], 16;\n" :: "r"(sa), "l"(gmem));
}
#define CP_COMMIT() asm volatile("cp.async.commit_group;\n" ::: "memory")
#define CP_WAIT1()  asm volatile("cp.async.wait_group 1;\n" ::: "memory")

// ---------------- preproc mega-kernel (elementwise, region dispatch) ----------
#define R0 131072     /* f2h + mean  : B*D            */
#define R1 262144     /* ench        : A*D/4          */
#define R2 1572864    /* wcath       : G4*XH/4        */
#define R3 1286144    /* clsh        : VPAD*H/4       */
#define R4 327680     /* smallwh     : NSMALL*H/4     */
#define R5 524288     /* hcwh        : 2H*D/4         */
#define R6 155648     /* embh        : B*T*E/4        */
#define R7 2560       /* biases + barrier reset       */
#define N_ELEM (R0+R1+R2+R3+R4+R5+R6+R7)   /* 4262400 = 16650*256 */

__global__ void k_prep_elem(
    const float* __restrict__ f,     const float* __restrict__ enc_w,
    const float* __restrict__ W_ih,  const float* __restrict__ b_ih,
    const float* __restrict__ W_hh,  const float* __restrict__ b_hh,
    const float* __restrict__ cls_w,
    const float* __restrict__ dec_w, const float* __restrict__ dec_b,
    const float* __restrict__ fb_w,  const float* __restrict__ fb_b,
    const float* __restrict__ h_fc_w,const float* __restrict__ h_fc_b,
    const float* __restrict__ c_fc_w,const float* __restrict__ c_fc_b,
    const float* __restrict__ emb,   const int* __restrict__ captions)
{
    int idx = blockIdx.x * 256 + threadIdx.x;

    if (idx < R0) {
        int b = idx >> 11, d = idx & (D-1);
        const float* p = f + (size_t)b*P*D + d;
        __half* o = g_featsh + (size_t)b*P*D + d;
        float s = 0.f;
        #pragma unroll 4
        for (int q = 0; q < P; q++) {
            float v = p[(size_t)q*D];
            s += v;
            o[(size_t)q*D] = __float2half(v);
        }
        g_meanfh[idx] = __float2half(s * (1.f/196.f));
        return;
    }
    idx -= R0;
    if (idx < R1) {
        size_t i = (size_t)idx * 4;
        st_half4(g_encwh + i, *(const float4*)(enc_w + i));
        return;
    }
    idx -= R1;
    if (idx < R2) {
        int j = idx / (XH/4);
        int k = (idx % (XH/4)) * 4;
        float4 v = (k < E + D) ? *(const float4*)(W_ih + (size_t)j*(E+D) + k)
                               : *(const float4*)(W_hh + (size_t)j*H + (k - (E+D)));
        st_half4(g_Wcath + (size_t)j*XH + k, v);
        return;
    }
    idx -= R2;
    if (idx < R3) {
        int n = idx >> 7, k = (idx & 127) * 4;
        float4 v = make_float4(0.f,0.f,0.f,0.f);
        if (n < V) v = *(const float4*)(cls_w + (size_t)n*H + k);
        st_half4(g_clswh + (size_t)n*H + k, v);
        return;
    }
    idx -= R3;
    if (idx < R4) {
        int n = idx >> 7, k = (idx & 127) * 4;
        const float* src = (n < A_DIM) ? dec_w + (size_t)n*H : fb_w + (size_t)(n - A_DIM)*H;
        st_half4(g_smallw + (size_t)n*H + k, *(const float4*)(src + k));
        return;
    }
    idx -= R4;
    if (idx < R5) {
        int n = idx >> 9, k = (idx & 511) * 4;
        const float* src = (n < H) ? h_fc_w + (size_t)n*D : c_fc_w + (size_t)(n - H)*D;
        st_half4(g_hcwh + (size_t)n*D + k, *(const float4*)(src + k));
        return;
    }
    idx -= R5;
    if (idx < R6) {
        int row = idx >> 7, e4 = (idx & 127) * 4;
        int b = row / T, t = row % T;
        int tok = captions[b*LCAP + t];
        st_half4(g_embh + (size_t)row*E + e4, *(const float4*)(emb + (size_t)tok*E + e4));
        return;
    }
    idx -= R6;
    if (idx < R7) {
        if (idx == 0) *(unsigned*)&g_bar = 0u;       // barrier reset (was k_zero)
        if (idx < G4)  g_bcat[idx]   = b_ih[idx] + b_hh[idx];
        g_smallb[idx] = (idx < A_DIM) ? dec_b[idx] : fb_b[idx - A_DIM];
        if (idx < 2*H) g_hcb[idx]    = (idx < H) ? h_fc_b[idx] : c_fc_b[idx - H];
    }
}

// ---------------- HMMA core (cp.async 3-stage pipeline) ------------------------
__device__ __forceinline__ void mma16816(float c[4], const unsigned a[4], const unsigned b[2])
{
    asm volatile(
        "mma.sync.aligned.m16n8k16.row.col.f32.f16.f16.f32 "
        "{%0,%1,%2,%3}, {%4,%5,%6,%7}, {%8,%9}, {%0,%1,%2,%3};"
        : "+f"(c[0]), "+f"(c[1]), "+f"(c[2]), "+f"(c[3])
        : "r"(a[0]), "r"(a[1]), "r"(a[2]), "r"(a[3]), "r"(b[0]), "r"(b[1]));
}

struct SmemP { __half As[STAGES][64][40]; __half Ws[STAGES][64][40]; };

__device__ __forceinline__ void hmma_tile(
    const __half* __restrict__ Aptr, int ldA,
    const __half* __restrict__ Wptr, int ldW,
    SmemP* sm, float acc[2][2][4], int K)
{
    const int tid  = threadIdx.x;
    const int lane = tid & 31;
    const int wid  = tid >> 5;
    const int wm   = wid >> 2;
    const int wn   = wid & 3;
    const int grp  = lane >> 2;
    const int qp   = lane & 3;
    const int lrow = tid >> 2;
    const int lcol = (tid & 3) * 8;

    const __half* ap = Aptr + (size_t)lrow*ldA + lcol;
    const __half* wp = Wptr + (size_t)lrow*ldW + lcol;
    const int nch = K >> 5;

    // make stale stages safe to overwrite before first wait
    __syncthreads();

    #pragma unroll
    for (int s = 0; s < STAGES-1; s++) {
        cp16(&sm->As[s][lrow][lcol], ap + s*32);
        cp16(&sm->Ws[s][lrow][lcol], wp + s*32);
        CP_COMMIT();
    }

    for (int c = 0; c < nch; c++) {
        const int st = c % STAGES;
        CP_WAIT1();                 // stage c landed (≤1 group pending)
        __syncthreads();

        #pragma unroll
        for (int ks = 0; ks < 2; ks++) {
            const int kb = 16*ks + 2*qp;
            unsigned afr[2][4], bfr[2][2];
            #pragma unroll
            for (int mf = 0; mf < 2; mf++) {
                const int r = 32*wm + 16*mf + grp;
                afr[mf][0] = *(const unsigned*)&sm->As[st][r    ][kb    ];
                afr[mf][1] = *(const unsigned*)&sm->As[st][r + 8][kb    ];
                afr[mf][2] = *(const unsigned*)&sm->As[st][r    ][kb + 8];
                afr[mf][3] = *(const unsigned*)&sm->As[st][r + 8][kb + 8];
            }
            #pragma unroll
            for (int nf = 0; nf < 2; nf++) {
                const int r = 16*wn + 8*nf + grp;
                bfr[nf][0] = *(const unsigned*)&sm->Ws[st][r][kb    ];
                bfr[nf][1] = *(const unsigned*)&sm->Ws[st][r][kb + 8];
            }
            #pragma unroll
            for (int mf = 0; mf < 2; mf++)
                #pragma unroll
                for (int nf = 0; nf < 2; nf++)
                    mma16816(acc[mf][nf], afr[mf], bfr[nf]);
        }

        const int nc = c + STAGES - 1;
        if (nc < nch) {
            const int st2 = nc % STAGES;
            cp16(&sm->As[st2][lrow][lcol], ap + nc*32);
            cp16(&sm->Ws[st2][lrow][lcol], wp + nc*32);
        }
        CP_COMMIT();
    }
}

// ---------------- preproc GEMMs: att1 (0..1567) + h0/c0 (1568..1583) ----------
__global__ void __launch_bounds__(256, 2) k_prep_gemm(const float* __restrict__ enc_b)
{
    __shared__ SmemP sm;
    const int tid  = threadIdx.x;
    const int lane = tid & 31;
    const int wid  = tid >> 5;
    const int wm = wid >> 2, wn = wid & 3, grp = lane >> 2, qp = lane & 3;
    const int tile = blockIdx.x;
    float acc[2][2][4] = {};

    if (tile < 1568) {
        const int m0 = (tile >> 3) * 64;
        const int n0 = (tile & 7) * 64;
        hmma_tile(g_featsh + (size_t)m0*D, D, g_encwh + (size_t)n0*D, D, &sm, acc, D);
        #pragma unroll
        for (int mf = 0; mf < 2; mf++)
            #pragma unroll
            for (int nf = 0; nf < 2; nf++)
                #pragma unroll
                for (int q = 0; q < 4; q++) {
                    int m = m0 + 32*wm + 16*mf + grp + (q >> 1)*8;
                    int n = n0 + 16*wn + 8*nf + 2*qp + (q & 1);
                    g_att1h[(size_t)m*A_DIM + n] = __float2half(acc[mf][nf][q] + enc_b[n]);
                }
    } else {
        const int n0 = (tile - 1568) * 64;
        hmma_tile(g_meanfh, D, g_hcwh + (size_t)n0*D, D, &sm, acc, D);
        #pragma unroll
        for (int mf = 0; mf < 2; mf++)
            #pragma unroll
            for (int nf = 0; nf < 2; nf++)
                #pragma unroll
                for (int q = 0; q < 4; q++) {
                    int m = 32*wm + 16*mf + grp + (q >> 1)*8;
                    int n = n0 + 16*wn + 8*nf + 2*qp + (q & 1);
                    float v = acc[mf][nf][q] + g_hcb[n];
                    if (n < H) g_h0[(size_t)m*H + n] = v;
                    else       g_c [(size_t)m*H + n - H] = v;
                }
    }
}

// ---------------- grid barrier with HW-sleep backoff ---------------------------
__device__ __forceinline__ void gbar(int nblk, int& target)
{
    __syncthreads();
    target += nblk;
    if (threadIdx.x == 0) {
        __threadfence();
        atomicAdd((unsigned*)&g_bar, 1u);
        while (g_bar < (unsigned)target)
            __nanosleep(128);
        __threadfence();
    }
    __syncthreads();
}

// ---------------- persistent decode --------------------------------------------
__global__ void __launch_bounds__(256, 2) k_decode(
    const int*   __restrict__ lengths,
    const float* __restrict__ attw,
    const float* __restrict__ attb,
    const float* __restrict__ cls_b,
    float* __restrict__ outy,
    float* __restrict__ outa)
{
    __shared__ SmemP sm;
    __shared__ float sred[256];
    __shared__ float sal[256];
    const int nblk = gridDim.x;
    const int bid  = blockIdx.x;
    const int tid  = threadIdx.x;
    const int lane = tid & 31;
    const int wid  = tid >> 5;
    const int wm = wid >> 2, wn = wid & 3, grp = lane >> 2, qp = lane & 3;
    int target = 0;

    // ---- init: xhh = [emb(t=0) | - | h0]
    for (int i = bid*256 + tid; i < B*H; i += nblk*256) {
        const int b = i >> 9, j = i & (H-1);
        g_xhh[(size_t)b*XH + j]         = g_embh[(size_t)(b*T)*E + j];
        g_xhh[(size_t)b*XH + E + D + j] = __float2half(g_h0[i]);
    }
    gbar(nblk, target);

    for (int t = 0; t < T; t++) {
        // ==== Phase A: small (0..39) + gates emb|h (40..103) + cls(t-1) (104..260)
        const int ntA = (t > 0) ? 261 : 104;
        for (int tile = bid; tile < ntA; tile += nblk) {
            float acc[2][2][4] = {};
            if (tile < 40) {
                const int n0 = tile * 64;
                hmma_tile(g_xhh + (E + D), XH, g_smallw + (size_t)n0*H, H, &sm, acc, H);
                #pragma unroll
                for (int mf = 0; mf < 2; mf++)
                    #pragma unroll
                    for (int nf = 0; nf < 2; nf++)
                        #pragma unroll
                        for (int q = 0; q < 4; q++) {
                            int m = 32*wm + 16*mf + grp + (q >> 1)*8;
                            int n = n0 + 16*wn + 8*nf + 2*qp + (q & 1);
                            float v = acc[mf][nf][q] + g_smallb[n];
                            if (n >= A_DIM) v = 1.f / (1.f + expf(-v));
                            g_small_out[(size_t)m*NSMALL + n] = v;
                        }
            } else if (tile < 104) {
                const int it = tile - 40;
                const int n0 = (it & 31) * 64;
                const int part = it >> 5;
                const int koff = part ? (E + D) : 0;
                hmma_tile(g_xhh + koff, XH, g_Wcath + (size_t)n0*XH + koff, XH, &sm, acc, H);
                #pragma unroll
                for (int mf = 0; mf < 2; mf++)
                    #pragma unroll
                    for (int nf = 0; nf < 2; nf++)
                        #pragma unroll
                        for (int q = 0; q < 4; q++) {
                            int m = 32*wm + 16*mf + grp + (q >> 1)*8;
                            int n = n0 + 16*wn + 8*nf + 2*qp + (q & 1);
                            g_gparts[(size_t)part*B*G4 + (size_t)m*G4 + n] = acc[mf][nf][q];
                        }
            } else {
                const int n0 = (tile - 104) * 64;
                hmma_tile(g_xhh + (E + D), XH, g_clswh + (size_t)n0*H, H, &sm, acc, H);
                const int tp = t - 1;
                #pragma unroll
                for (int mf = 0; mf < 2; mf++)
                    #pragma unroll
                    for (int nf = 0; nf < 2; nf++)
                        #pragma unroll
                        for (int q = 0; q < 4; q++) {
                            int m = 32*wm + 16*mf + grp + (q >> 1)*8;
                            int n = n0 + 16*wn + 8*nf + 2*qp + (q & 1);
                            if (n < V) {
                                int act = tp < (lengths[m] - 1);
                                outy[(size_t)m*T*V + (size_t)tp*V + n] =
                                    act ? (acc[mf][nf][q] + cls_b[n]) : 0.f;
                            }
                        }
            }
        }
        gbar(nblk, target);

        // ==== Phase B1: e scores
        for (int idx = bid*8 + wid; idx < B*P; idx += nblk*8) {
            const int b = idx / P;
            const __half2* a1 = (const __half2*)(g_att1h + (size_t)idx * A_DIM);
            const float2*  a2 = (const float2*)(g_small_out + (size_t)b * NSMALL);
            const float2*  aw = (const float2*)attw;
            float s = 0.f;
            #pragma unroll
            for (int a = lane; a < A_DIM/2; a += 32) {
                float2 v1 = __half22float2(a1[a]);
                float2 v2 = a2[a];
                float2 w2 = aw[a];
                float x = v1.x + v2.x, y = v1.y + v2.y;
                if (x > 0.f) s += x * w2.x;
                if (y > 0.f) s += y * w2.y;
            }
            #pragma unroll
            for (int o = 16; o; o >>= 1) s += __shfl_xor_sync(0xffffffffu, s, o);
            if (lane == 0) g_e[idx] = s + attb[0];
        }
        gbar(nblk, target);

        // ==== Phase B2: softmax + awe (256 tiles = (b, chunk of 512))
        for (int tile = bid; tile < B*4; tile += nblk) {
            const int b = tile >> 2, chunk = tile & 3;
            float ev = (tid < P) ? g_e[b*P + tid] : -1e30f;
            sred[tid] = ev; __syncthreads();
            for (int s2 = 128; s2 > 0; s2 >>= 1) {
                if (tid < s2) sred[tid] = fmaxf(sred[tid], sred[tid + s2]);
                __syncthreads();
            }
            float mx = sred[0]; __syncthreads();
            float ex = (tid < P) ? expf(ev - mx) : 0.f;
            sred[tid] = ex; __syncthreads();
            for (int s2 = 128; s2 > 0; s2 >>= 1) {
                if (tid < s2) sred[tid] += sred[tid + s2];
                __syncthreads();
            }
            float inv = 1.f / sred[0];
            __syncthreads();
            if (tid < P) sal[tid] = ex * inv;
            __syncthreads();

            // awe with deep MLP: 4 accumulators, unrolled 4-wide (196 = 49*4)
            const __half2* fb = (const __half2*)g_featsh + (size_t)b*P*(D/2) + chunk*256 + tid;
            float2 s0 = {0.f,0.f}, s1 = {0.f,0.f}, s2v = {0.f,0.f}, s3 = {0.f,0.f};
            #pragma unroll 4
            for (int p = 0; p < 196; p += 4) {
                float2 f0 = __half22float2(fb[(size_t)(p+0)*(D/2)]);
                float2 f1 = __half22float2(fb[(size_t)(p+1)*(D/2)]);
                float2 f2 = __half22float2(fb[(size_t)(p+2)*(D/2)]);
                float2 f3 = __half22float2(fb[(size_t)(p+3)*(D/2)]);
                s0.x += sal[p+0]*f0.x; s0.y += sal[p+0]*f0.y;
                s1.x += sal[p+1]*f1.x; s1.y += sal[p+1]*f1.y;
                s2v.x += sal[p+2]*f2.x; s2v.y += sal[p+2]*f2.y;
                s3.x += sal[p+3]*f3.x; s3.y += sal[p+3]*f3.y;
            }
            float2 acc2 = make_float2((s0.x+s1.x)+(s2v.x+s3.x), (s0.y+s1.y)+(s2v.y+s3.y));
            const int d = chunk*512 + 2*tid;
            acc2.x *= g_small_out[(size_t)b*NSMALL + A_DIM + d];
            acc2.y *= g_small_out[(size_t)b*NSMALL + A_DIM + d + 1];
            *(__half2*)&g_xhh[(size_t)b*XH + E + d] = __floats2half2_rn(acc2.x, acc2.y);

            if (chunk == 0 && tid < P) {
                int act = t < (lengths[b] - 1);
                outa[((size_t)b*T + t)*P + tid] = act ? sal[tid] : 0.f;
            }
            __syncthreads();
        }
        gbar(nblk, target);

        // ==== Phase C: gates awe-part, 32 n-tiles x split-4 over K=2048
        for (int tile = bid; tile < 128; tile += nblk) {
            const int n0 = (tile & 31) * 64;
            const int ks = tile >> 5;
            const int koff = E + ks*512;
            float acc[2][2][4] = {};
            hmma_tile(g_xhh + koff, XH, g_Wcath + (size_t)n0*XH + koff, XH, &sm, acc, 512);
            #pragma unroll
            for (int mf = 0; mf < 2; mf++)
                #pragma unroll
                for (int nf = 0; nf < 2; nf++)
                    #pragma unroll
                    for (int q = 0; q < 4; q++) {
                        int m = 32*wm + 16*mf + grp + (q >> 1)*8;
                        int n = n0 + 16*wn + 8*nf + 2*qp + (q & 1);
                        g_gparts[(size_t)(2 + ks)*B*G4 + (size_t)m*G4 + n] = acc[mf][nf][q];
                    }
        }
        gbar(nblk, target);

        // ==== Phase D: LSTM pointwise + stage next emb
        for (int i = bid*256 + tid; i < B*H; i += nblk*256) {
            const int b = i >> 9, j = i & (H-1);
            float gi = g_bcat[j], gf = g_bcat[j + H], gg = g_bcat[j + 2*H], go = g_bcat[j + 3*H];
            #pragma unroll
            for (int s = 0; s < GP_SLOTS; s++) {
                const float* pp = g_gparts + (size_t)s*B*G4 + (size_t)b*G4;
                gi += pp[j]; gf += pp[j + H]; gg += pp[j + 2*H]; go += pp[j + 3*H];
            }
            float si = 1.f / (1.f + expf(-gi));
            float sf = 1.f / (1.f + expf(-gf));
            float so = 1.f / (1.f + expf(-go));
            float c2 = sf * g_c[i] + si * tanhf(gg);
            float h2 = so * tanhf(c2);
            g_c[i] = c2;
            g_xhh[(size_t)b*XH + E + D + j] = __float2half(h2);
            if (t + 1 < T) g_xhh[(size_t)b*XH + j] = g_embh[(size_t)(b*T + (t+1))*E + j];
        }
        gbar(nblk, target);
    }

    // ---- final cls (t = T-1)
    for (int tile = bid; tile < 157; tile += nblk) {
        const int n0 = tile * 64;
        float acc[2][2][4] = {};
        hmma_tile(g_xhh + (E + D), XH, g_clswh + (size_t)n0*H, H, &sm, acc, H);
        const int tp = T - 1;
        #pragma unroll
        for (int mf = 0; mf < 2; mf++)
            #pragma unroll
            for (int nf = 0; nf < 2; nf++)
                #pragma unroll
                for (int q = 0; q < 4; q++) {
                    int m = 32*wm + 16*mf + grp + (q >> 1)*8;
                    int n = n0 + 16*wn + 8*nf + 2*qp + (q & 1);
                    if (n < V) {
                        int act = tp < (lengths[m] - 1);
                        outy[(size_t)m*T*V + (size_t)tp*V + n] =
                            act ? (acc[mf][nf][q] + cls_b[n]) : 0.f;
                    }
                }
    }
}

// ---------------- host driver ---------------------------------------------------
extern "C" void kernel_launch(void* const* d_in, const int* in_sizes, int n_in,
                              void* d_out, int out_size)
{
    const float* features = (const float*)d_in[0];
    const int*   captions = (const int*)  d_in[1];
    const int*   lengths  = (const int*)  d_in[2];
    const float* emb      = (const float*)d_in[3];
    const float* W_ih     = (const float*)d_in[4];
    const float* b_ih     = (const float*)d_in[5];
    const float* W_hh     = (const float*)d_in[6];
    const float* b_hh     = (const float*)d_in[7];
    const float* h_fc_w   = (const float*)d_in[8];
    const float* h_fc_b   = (const float*)d_in[9];
    const float* c_fc_w   = (const float*)d_in[10];
    const float* c_fc_b   = (const float*)d_in[11];
    const float* f_beta_w = (const float*)d_in[12];
    const float* f_beta_b = (const float*)d_in[13];
    const float* cls_w    = (const float*)d_in[14];
    const float* cls_b    = (const float*)d_in[15];
    const float* enc_w    = (const float*)d_in[16];
    const float* enc_b    = (const float*)d_in[17];
    const float* dec_w    = (const float*)d_in[18];
    const float* dec_b    = (const float*)d_in[19];
    const float* att_w    = (const float*)d_in[20];
    const float* att_b    = (const float*)d_in[21];

    float* outy = (float*)d_out;
    float* outa = outy + (size_t)B*T*V;

    int nsm = 148;
    cudaDeviceGetAttribute(&nsm, cudaDevAttrMultiProcessorCount, 0);

    k_prep_elem<<<N_ELEM/256, 256>>>(features, enc_w, W_ih, b_ih, W_hh, b_hh, cls_w,
                                     dec_w, dec_b, f_beta_w, f_beta_b,
                                     h_fc_w, h_fc_b, c_fc_w, c_fc_b, emb, captions);
    k_prep_gemm<<<1584, 256>>>(enc_b);
    k_decode   <<<2*nsm, 256>>>(lengths, att_w, att_b, cls_b, outy, outa);
}